// round 3
// baseline (speedup 1.0000x reference)
#include <cuda_runtime.h>

#define NB 8
#define NR 16
#define NC 512
#define NS 512
#define NK 64
#define NVEC (NB*NR*NC)          /* 65536 */
#define NSPLIT 4                 /* codebook split factor */
#define SC (NS/NSPLIT)           /* 128 codes per block */
#define NBLK2 512                /* combine-kernel blocks */

#define OFF_Z      (NVEC*NK)         /* 4194304 */
#define OFF_COMMIT (OFF_Z + NVEC)    /* 4259840 */
#define OFF_CB     (OFF_COMMIT + 1)  /* 4259841 */
#define OFF_ERR    (OFF_CB + 1)      /* 4259842 */

typedef unsigned long long u64;

__device__ float g_c[NS * NK];        // codebook c = c_sum / max(count, 0.01)
__device__ float g_cnh[NS];           // 0.5 * ||c_s||^2
__device__ float g_bscore[NSPLIT][NVEC];  // per-split best score
__device__ int   g_bidx[NSPLIT][NVEC];    // per-split best index
__device__ float g_vn[NVEC];          // ||v||^2
__device__ float g_partial[NBLK2];    // per-block errs2 sums

// ---- packed fp32x2 helpers (Blackwell FFMA2 / FADD2) ----------------------
__device__ __forceinline__ u64 fma2(u64 a, u64 b, u64 c) {
    u64 d;
    asm("fma.rn.f32x2 %0, %1, %2, %3;" : "=l"(d) : "l"(a), "l"(b), "l"(c));
    return d;
}
__device__ __forceinline__ u64 add2(u64 a, u64 b) {
    u64 d;
    asm("add.rn.f32x2 %0, %1, %2;" : "=l"(d) : "l"(a), "l"(b));
    return d;
}
__device__ __forceinline__ float hsum2(u64 a) {
    float lo, hi;
    asm("mov.b64 {%0, %1}, %2;" : "=f"(lo), "=f"(hi) : "l"(a));
    return lo + hi;
}

// ---------------------------------------------------------------------------
// Kernel 1: build codebook + half-norms. One warp per code.
// ---------------------------------------------------------------------------
__global__ void __launch_bounds__(128) vq_prep(const float* __restrict__ c_sum,
                                               const float* __restrict__ c_count) {
    int warp = (blockIdx.x * blockDim.x + threadIdx.x) >> 5;
    int lane = threadIdx.x & 31;
    if (warp >= NS) return;
    float inv = 1.0f / fmaxf(c_count[warp], 0.01f);
    float a = c_sum[warp * NK + lane] * inv;
    float b = c_sum[warp * NK + 32 + lane] * inv;
    g_c[warp * NK + lane] = a;
    g_c[warp * NK + 32 + lane] = b;
    float nh = a * a + b * b;
#pragma unroll
    for (int o = 16; o; o >>= 1) nh += __shfl_xor_sync(0xffffffffu, nh, o);
    if (lane == 0) g_cnh[warp] = 0.5f * nh;
}

// ---------------------------------------------------------------------------
// Kernel 2: partial nearest-code search. blockIdx.y selects a 128-code split.
// 128 threads/block, 2 vectors/thread; 32KB smem tile loaded once.
// ---------------------------------------------------------------------------
__global__ void __launch_bounds__(128) vq_search(const float* __restrict__ vecs) {
    __shared__ __align__(16) float sc[SC * NK];   // 32 KB
    __shared__ float scn[SC];

    int tid = threadIdx.x;
    int split = blockIdx.y;
    int n0 = blockIdx.x * 256 + tid;
    int n1 = n0 + 128;

    // load this split's 128 codes into smem (2048 float4, 16 per thread)
    {
        const float4* gc = reinterpret_cast<const float4*>(g_c + split * SC * NK);
        float4* scv = reinterpret_cast<float4*>(sc);
#pragma unroll
        for (int i = 0; i < 16; i++) scv[tid + 128 * i] = gc[tid + 128 * i];
        scn[tid] = g_cnh[split * SC + tid];
    }

    // load 2 vectors into registers as packed fp32 pairs
    u64 v0[NK / 2], v1[NK / 2];
    const ulonglong2* p0 = reinterpret_cast<const ulonglong2*>(vecs + (size_t)n0 * NK);
    const ulonglong2* p1 = reinterpret_cast<const ulonglong2*>(vecs + (size_t)n1 * NK);
    u64 nv0a = 0, nv0b = 0, nv1a = 0, nv1b = 0;
#pragma unroll
    for (int i = 0; i < 16; i++) {
        ulonglong2 a = p0[i];
        v0[2 * i] = a.x;  v0[2 * i + 1] = a.y;
        nv0a = fma2(a.x, a.x, nv0a);
        nv0b = fma2(a.y, a.y, nv0b);
        ulonglong2 b = p1[i];
        v1[2 * i] = b.x;  v1[2 * i + 1] = b.y;
        nv1a = fma2(b.x, b.x, nv1a);
        nv1b = fma2(b.y, b.y, nv1b);
    }
    if (split == 0) {
        g_vn[n0] = hsum2(add2(nv0a, nv0b));
        g_vn[n1] = hsum2(add2(nv1a, nv1b));
    }

    __syncthreads();

    float best0 = -3.4e38f, best1 = -3.4e38f;
    int i0 = 0, i1 = 0;

#pragma unroll 2
    for (int s = 0; s < SC; s++) {
        float cn = scn[s];
        const ulonglong2* cp = reinterpret_cast<const ulonglong2*>(sc + s * NK);
        u64 a00 = 0, a01 = 0, a10 = 0, a11 = 0;
#pragma unroll
        for (int i = 0; i < 16; i++) {
            ulonglong2 c2 = cp[i];
            a00 = fma2(v0[2 * i],     c2.x, a00);
            a01 = fma2(v0[2 * i + 1], c2.y, a01);
            a10 = fma2(v1[2 * i],     c2.x, a10);
            a11 = fma2(v1[2 * i + 1], c2.y, a11);
        }
        float d0 = hsum2(add2(a00, a01)) - cn;
        float d1 = hsum2(add2(a10, a11)) - cn;
        if (d0 > best0) { best0 = d0; i0 = s; }
        if (d1 > best1) { best1 = d1; i1 = s; }
    }

    g_bscore[split][n0] = best0;
    g_bidx[split][n0] = split * SC + i0;
    g_bscore[split][n1] = best1;
    g_bidx[split][n1] = split * SC + i1;
}

// ---------------------------------------------------------------------------
// Kernel 3: combine splits — final argmin, gather, errs2, reduction.
// ---------------------------------------------------------------------------
__global__ void __launch_bounds__(128) vq_combine(float* __restrict__ out) {
    __shared__ float red[128];
    int tid = threadIdx.x;
    int n = blockIdx.x * 128 + tid;

    float best = g_bscore[0][n];
    int idx = g_bidx[0][n];
#pragma unroll
    for (int p = 1; p < NSPLIT; p++) {
        float b = g_bscore[p][n];
        int i = g_bidx[p][n];
        if (b > best) { best = b; idx = i; }
    }

    float err = fmaxf(g_vn[n] - 2.0f * best, 0.0f);

    // gather codeword
    const float4* c = reinterpret_cast<const float4*>(g_c + (size_t)idx * NK);
    float4* o = reinterpret_cast<float4*>(out + (size_t)n * NK);
#pragma unroll
    for (int i = 0; i < 16; i++) o[i] = c[i];

    out[OFF_Z + n] = (float)idx;
    out[OFF_ERR + n] = err;

    // deterministic block reduction of errs2
    red[tid] = err;
    __syncthreads();
#pragma unroll
    for (int off = 64; off > 0; off >>= 1) {
        if (tid < off) red[tid] += red[tid + off];
        __syncthreads();
    }
    if (tid == 0) g_partial[blockIdx.x] = red[0];
}

// ---------------------------------------------------------------------------
// Kernel 4: finalize scalars (deterministic sequential sum).
// ---------------------------------------------------------------------------
__global__ void vq_finalize(float* __restrict__ out) {
    if (threadIdx.x == 0 && blockIdx.x == 0) {
        double d = 0.0;
        for (int i = 0; i < NBLK2; i++) d += (double)g_partial[i];
        out[OFF_COMMIT] = (float)(d / (double)NVEC);
        out[OFF_CB] = 0.0f;   // l_codebook is identically 0 in forward value
    }
}

extern "C" void kernel_launch(void* const* d_in, const int* in_sizes, int n_in,
                              void* d_out, int out_size) {
    const float* vecs    = (const float*)d_in[0];
    const float* c_sum   = (const float*)d_in[1];
    const float* c_count = (const float*)d_in[2];
    float* out = (float*)d_out;

    vq_prep<<<128, 128>>>(c_sum, c_count);        // 512 warps = 512 codes
    dim3 grid(NVEC / 256, NSPLIT);
    vq_search<<<grid, 128>>>(vecs);               // 1024 blocks
    vq_combine<<<NBLK2, 128>>>(out);
    vq_finalize<<<1, 32>>>(out);
}

// round 4
// speedup vs baseline: 1.2453x; 1.2453x over previous
#include <cuda_runtime.h>

#define NB 8
#define NR 16
#define NC 512
#define NS 512
#define NK 64
#define NVEC (NB*NR*NC)          /* 65536 */
#define NSPLIT 4                 /* codebook split factor */
#define SC (NS/NSPLIT)           /* 128 codes per split */
#define VB 256                   /* vectors per work unit */
#define NUNITS (NSPLIT * (NVEC/VB))  /* 1024 */
#define GRID_SEARCH 444          /* 148 SMs * 3 blocks */
#define NBLK2 512                /* combine-kernel blocks */

#define OFF_Z      (NVEC*NK)         /* 4194304 */
#define OFF_COMMIT (OFF_Z + NVEC)    /* 4259840 */
#define OFF_CB     (OFF_COMMIT + 1)  /* 4259841 */
#define OFF_ERR    (OFF_CB + 1)      /* 4259842 */

typedef unsigned long long u64;

__device__ float g_c[NS * NK];            // codebook
__device__ float g_cnh[NS];               // 0.5*||c||^2
__device__ float g_bscore[NSPLIT][NVEC];  // per-split best score
__device__ int   g_bidx[NSPLIT][NVEC];    // per-split best index
__device__ float g_vn[NVEC];              // ||v||^2
__device__ float g_partial[NBLK2];        // per-block errs2 sums
__device__ int   g_ctr;                   // work-steal counter

// ---- packed fp32x2 helpers (Blackwell FFMA2 / FADD2) ----------------------
__device__ __forceinline__ u64 fma2(u64 a, u64 b, u64 c) {
    u64 d;
    asm("fma.rn.f32x2 %0, %1, %2, %3;" : "=l"(d) : "l"(a), "l"(b), "l"(c));
    return d;
}
__device__ __forceinline__ u64 add2(u64 a, u64 b) {
    u64 d;
    asm("add.rn.f32x2 %0, %1, %2;" : "=l"(d) : "l"(a), "l"(b));
    return d;
}
__device__ __forceinline__ float hsum2(u64 a) {
    float lo, hi;
    asm("mov.b64 {%0, %1}, %2;" : "=f"(lo), "=f"(hi) : "l"(a));
    return lo + hi;
}

// ---------------------------------------------------------------------------
// Kernel 1: build codebook + half-norms; reset work counter.
// ---------------------------------------------------------------------------
__global__ void __launch_bounds__(128) vq_prep(const float* __restrict__ c_sum,
                                               const float* __restrict__ c_count) {
    if (blockIdx.x == 0 && threadIdx.x == 0) g_ctr = 0;
    int warp = (blockIdx.x * blockDim.x + threadIdx.x) >> 5;
    int lane = threadIdx.x & 31;
    if (warp >= NS) return;
    float inv = 1.0f / fmaxf(c_count[warp], 0.01f);
    float a = c_sum[warp * NK + lane] * inv;
    float b = c_sum[warp * NK + 32 + lane] * inv;
    g_c[warp * NK + lane] = a;
    g_c[warp * NK + 32 + lane] = b;
    float nh = a * a + b * b;
#pragma unroll
    for (int o = 16; o; o >>= 1) nh += __shfl_xor_sync(0xffffffffu, nh, o);
    if (lane == 0) g_cnh[warp] = 0.5f * nh;
}

// ---------------------------------------------------------------------------
// Kernel 2: persistent partial nearest-code search with work stealing.
// Unit u = (split, vecblock); split-major so tile reloads are rare.
// ---------------------------------------------------------------------------
__global__ void __launch_bounds__(128, 3) vq_search(const float* __restrict__ vecs) {
    __shared__ __align__(16) float sc[SC * NK];   // 32 KB
    __shared__ float scn[SC];
    __shared__ int s_u;
    __shared__ int s_cached;

    int tid = threadIdx.x;
    if (tid == 0) s_cached = -1;

    for (;;) {
        if (tid == 0) s_u = atomicAdd(&g_ctr, 1);
        __syncthreads();                 // publishes s_u; all lanes done with old tile
        int u = s_u;
        if (u >= NUNITS) return;
        int split = u >> 8;              // 256 vecblocks per split
        int vb = u & 255;

        if (s_cached != split) {
            const float4* gc = reinterpret_cast<const float4*>(g_c + split * SC * NK);
            float4* scv = reinterpret_cast<float4*>(sc);
#pragma unroll
            for (int i = 0; i < 16; i++) scv[tid + 128 * i] = gc[tid + 128 * i];
            scn[tid] = g_cnh[split * SC + tid];
            if (tid == 0) s_cached = split;
            __syncthreads();
        }

        int n0 = vb * VB + tid;
        int n1 = n0 + 128;

        u64 v0[NK / 2], v1[NK / 2];
        const ulonglong2* p0 = reinterpret_cast<const ulonglong2*>(vecs + (size_t)n0 * NK);
        const ulonglong2* p1 = reinterpret_cast<const ulonglong2*>(vecs + (size_t)n1 * NK);
        u64 nv0 = 0, nv1 = 0;
#pragma unroll
        for (int i = 0; i < 16; i++) {
            ulonglong2 a = p0[i];
            v0[2 * i] = a.x;  v0[2 * i + 1] = a.y;
            nv0 = fma2(a.x, a.x, nv0);
            nv0 = fma2(a.y, a.y, nv0);
            ulonglong2 b = p1[i];
            v1[2 * i] = b.x;  v1[2 * i + 1] = b.y;
            nv1 = fma2(b.x, b.x, nv1);
            nv1 = fma2(b.y, b.y, nv1);
        }
        if (split == 0) {
            g_vn[n0] = hsum2(nv0);
            g_vn[n1] = hsum2(nv1);
        }

        float best0 = -3.4e38f, best1 = -3.4e38f;
        int i0 = 0, i1 = 0;

#pragma unroll 2
        for (int s = 0; s < SC; s++) {
            float cn = scn[s];
            const ulonglong2* cp = reinterpret_cast<const ulonglong2*>(sc + s * NK);
            u64 a00 = 0, a01 = 0, a10 = 0, a11 = 0;
#pragma unroll
            for (int i = 0; i < 16; i++) {
                ulonglong2 c2 = cp[i];
                a00 = fma2(v0[2 * i],     c2.x, a00);
                a01 = fma2(v0[2 * i + 1], c2.y, a01);
                a10 = fma2(v1[2 * i],     c2.x, a10);
                a11 = fma2(v1[2 * i + 1], c2.y, a11);
            }
            float d0 = hsum2(add2(a00, a01)) - cn;
            float d1 = hsum2(add2(a10, a11)) - cn;
            if (d0 > best0) { best0 = d0; i0 = s; }
            if (d1 > best1) { best1 = d1; i1 = s; }
        }

        g_bscore[split][n0] = best0;
        g_bidx[split][n0] = split * SC + i0;
        g_bscore[split][n1] = best1;
        g_bidx[split][n1] = split * SC + i1;
    }
}

// ---------------------------------------------------------------------------
// Kernel 3: combine splits — final argmin, gather, errs2, block reduction.
// ---------------------------------------------------------------------------
__global__ void __launch_bounds__(128) vq_combine(float* __restrict__ out) {
    __shared__ float red[128];
    int tid = threadIdx.x;
    int n = blockIdx.x * 128 + tid;

    float best = g_bscore[0][n];
    int idx = g_bidx[0][n];
#pragma unroll
    for (int p = 1; p < NSPLIT; p++) {
        float b = g_bscore[p][n];
        int i = g_bidx[p][n];
        if (b > best) { best = b; idx = i; }
    }

    float err = fmaxf(g_vn[n] - 2.0f * best, 0.0f);

    const float4* c = reinterpret_cast<const float4*>(g_c + (size_t)idx * NK);
    float4* o = reinterpret_cast<float4*>(out + (size_t)n * NK);
#pragma unroll
    for (int i = 0; i < 16; i++) o[i] = c[i];

    out[OFF_Z + n] = (float)idx;
    out[OFF_ERR + n] = err;

    red[tid] = err;
    __syncthreads();
#pragma unroll
    for (int off = 64; off > 0; off >>= 1) {
        if (tid < off) red[tid] += red[tid + off];
        __syncthreads();
    }
    if (tid == 0) g_partial[blockIdx.x] = red[0];
}

// ---------------------------------------------------------------------------
// Kernel 4: finalize scalars — parallel deterministic tree reduction.
// ---------------------------------------------------------------------------
__global__ void __launch_bounds__(512) vq_finalize(float* __restrict__ out) {
    __shared__ float red[512];
    int tid = threadIdx.x;
    red[tid] = g_partial[tid];
    __syncthreads();
#pragma unroll
    for (int off = 256; off > 0; off >>= 1) {
        if (tid < off) red[tid] += red[tid + off];
        __syncthreads();
    }
    if (tid == 0) {
        out[OFF_COMMIT] = red[0] * (1.0f / (float)NVEC);
        out[OFF_CB] = 0.0f;   // l_codebook is identically 0 in forward value
    }
}

extern "C" void kernel_launch(void* const* d_in, const int* in_sizes, int n_in,
                              void* d_out, int out_size) {
    const float* vecs    = (const float*)d_in[0];
    const float* c_sum   = (const float*)d_in[1];
    const float* c_count = (const float*)d_in[2];
    float* out = (float*)d_out;

    vq_prep<<<128, 128>>>(c_sum, c_count);
    vq_search<<<GRID_SEARCH, 128>>>(vecs);
    vq_combine<<<NBLK2, 128>>>(out);
    vq_finalize<<<1, 512>>>(out);
}

// round 6
// speedup vs baseline: 2.1003x; 1.6865x over previous
#include <cuda_runtime.h>
#include <cuda_fp16.h>
#include <cstdint>

#define NS 512
#define NK 64
#define NVEC 65536
#define M_TILE 128
#define NCTA (NVEC / M_TILE)      /* 512 */

#define OFF_Z      (NVEC*NK)
#define OFF_COMMIT (OFF_Z + NVEC)
#define OFF_CB     (OFF_COMMIT + 1)
#define OFF_ERR    (OFF_CB + 1)

/* dynamic smem layout */
#define SM_A    0           /* 2 planes * 128 rows * 128B = 32768 */
#define SM_B    32768       /* 2 planes * 64 rows * 128B = 16384 */
#define SM_SCN  49152       /* 512 * 4 = 2048 */
#define SM_RED  51200       /* 4 warps * 4 = 16 */
#define SM_TOT  51232

__device__ float  g_c[NS * NK];          // fp32 codebook
__device__ float  g_cnh[NS];             // 0.5*||c||^2
__device__ __half g_ch[2][NS * NK];      // codebook fp16 planes (h0, h1)
__device__ __half g_vh[2][NVEC * NK];    // vector fp16 planes
__device__ float  g_vn[NVEC];            // ||v||^2
__device__ float  g_partial[NCTA];

__device__ __forceinline__ uint32_t smem_u32(const void* p) {
    uint32_t a;
    asm("{ .reg .u64 t; cvta.to.shared.u64 t, %1; cvt.u32.u64 %0, t; }" : "=r"(a) : "l"(p));
    return a;
}

__device__ __forceinline__ void ldsm_x4(uint32_t* r, uint32_t a) {
    asm volatile("ldmatrix.sync.aligned.m8n8.x4.shared.b16 {%0,%1,%2,%3}, [%4];"
                 : "=r"(r[0]), "=r"(r[1]), "=r"(r[2]), "=r"(r[3]) : "r"(a));
}
__device__ __forceinline__ void ldsm_x2(uint32_t* r, uint32_t a) {
    asm volatile("ldmatrix.sync.aligned.m8n8.x2.shared.b16 {%0,%1}, [%2];"
                 : "=r"(r[0]), "=r"(r[1]) : "r"(a));
}
__device__ __forceinline__ void mma16816(float* c, const uint32_t* a, const uint32_t* b) {
    asm volatile("mma.sync.aligned.m16n8k16.row.col.f32.f16.f16.f32 "
                 "{%0,%1,%2,%3}, {%4,%5,%6,%7}, {%8,%9}, {%0,%1,%2,%3};"
                 : "+f"(c[0]), "+f"(c[1]), "+f"(c[2]), "+f"(c[3])
                 : "r"(a[0]), "r"(a[1]), "r"(a[2]), "r"(a[3]), "r"(b[0]), "r"(b[1]));
}

__device__ __forceinline__ void hsplit(float x, __half& h0, __half& h1) {
    h0 = __float2half_rn(x);
    h1 = __float2half_rn(x - __half2float(h0));
}

// ---------------------------------------------------------------------------
// Kernel 1: codebook -> fp32 + half-norms + fp16 planes. One warp per code.
// ---------------------------------------------------------------------------
__global__ void __launch_bounds__(128) vq_prep_code(const float* __restrict__ c_sum,
                                                    const float* __restrict__ c_count) {
    int warp = (blockIdx.x * blockDim.x + threadIdx.x) >> 5;
    int lane = threadIdx.x & 31;
    if (warp >= NS) return;
    float inv = 1.0f / fmaxf(c_count[warp], 0.01f);
    float a = c_sum[warp * NK + lane] * inv;
    float b = c_sum[warp * NK + 32 + lane] * inv;
    g_c[warp * NK + lane] = a;
    g_c[warp * NK + 32 + lane] = b;
    __half h0, h1;
    hsplit(a, h0, h1);
    g_ch[0][warp * NK + lane] = h0;
    g_ch[1][warp * NK + lane] = h1;
    hsplit(b, h0, h1);
    g_ch[0][warp * NK + 32 + lane] = h0;
    g_ch[1][warp * NK + 32 + lane] = h1;
    float nh = a * a + b * b;
#pragma unroll
    for (int o = 16; o; o >>= 1) nh += __shfl_xor_sync(0xffffffffu, nh, o);
    if (lane == 0) g_cnh[warp] = 0.5f * nh;
}

// ---------------------------------------------------------------------------
// Kernel 2: vectors -> fp16 planes + ||v||^2. One thread per vector.
// ---------------------------------------------------------------------------
__global__ void __launch_bounds__(128) vq_prep_vec(const float* __restrict__ vecs) {
    int n = blockIdx.x * 128 + threadIdx.x;
    const float4* src = reinterpret_cast<const float4*>(vecs + (size_t)n * NK);
    float vn = 0.f;
#pragma unroll
    for (int i = 0; i < 8; i++) {
        float4 q0 = src[2 * i], q1 = src[2 * i + 1];
        float x[8] = {q0.x, q0.y, q0.z, q0.w, q1.x, q1.y, q1.z, q1.w};
        union { uint4 u; __half2 h[4]; } p0, p1;
#pragma unroll
        for (int j = 0; j < 4; j++) {
            __half a0, a1, b0, b1;
            hsplit(x[2 * j], a0, a1);
            hsplit(x[2 * j + 1], b0, b1);
            p0.h[j] = __halves2half2(a0, b0);
            p1.h[j] = __halves2half2(a1, b1);
            vn += x[2 * j] * x[2 * j] + x[2 * j + 1] * x[2 * j + 1];
        }
        reinterpret_cast<uint4*>(g_vh[0] + (size_t)n * NK)[i] = p0.u;
        reinterpret_cast<uint4*>(g_vh[1] + (size_t)n * NK)[i] = p1.u;
    }
    g_vn[n] = vn;
}

// ---------------------------------------------------------------------------
// Kernel 3: mma.sync search. CTA = 128 vectors vs 512 codes; 4 warps,
// warp w owns rows [w*32, w*32+32). fp16 2-plane split, 4 cross terms.
// ---------------------------------------------------------------------------
__global__ void __launch_bounds__(128) vq_mma(float* __restrict__ out) {
    extern __shared__ __align__(128) char smem[];
    uint32_t sb = smem_u32(smem);
    int tid = threadIdx.x;
    int wid = tid >> 5;
    int lane = tid & 31;
    int cta = blockIdx.x;

    // codebook half-norms -> smem
    for (int i = tid; i < NS; i += 128)
        reinterpret_cast<float*>(smem + SM_SCN)[i] = g_cnh[i];

    // A planes -> smem, XOR-swizzled 16B chunks (row stride 128B)
#pragma unroll
    for (int p = 0; p < 2; p++) {
        const uint4* src = reinterpret_cast<const uint4*>(g_vh[p] + (size_t)cta * M_TILE * NK);
        for (int i = tid; i < 1024; i += 128) {
            int row = i >> 3, ch = i & 7;
            *reinterpret_cast<uint4*>(smem + SM_A + p * 16384 + row * 128 +
                                      ((ch ^ (row & 7)) << 4)) = src[i];
        }
    }
    __syncthreads();

    // register-resident A fragments: [plane][mtile][kstep][4]
    uint32_t af[2][2][4][4];
    {
        int r = lane & 15;
        int hi = lane >> 4;
#pragma unroll
        for (int p = 0; p < 2; p++)
#pragma unroll
            for (int mt = 0; mt < 2; mt++) {
                int row = wid * 32 + mt * 16 + r;
#pragma unroll
                for (int k = 0; k < 4; k++) {
                    int ch = (2 * k + hi) ^ (row & 7);
                    ldsm_x4(af[p][mt][k], sb + SM_A + p * 16384 + row * 128 + ch * 16);
                }
            }
    }

    const float* scn = reinterpret_cast<const float*>(smem + SM_SCN);
    float best[4] = {-3.4e38f, -3.4e38f, -3.4e38f, -3.4e38f};
    int idx[4] = {0, 0, 0, 0};

    for (int tile = 0; tile < 8; tile++) {
        __syncthreads();   // previous tile fully consumed (mma.sync is synchronous)
#pragma unroll
        for (int p = 0; p < 2; p++) {
            const uint4* src = reinterpret_cast<const uint4*>(g_ch[p] + (size_t)tile * 64 * NK);
            for (int i = tid; i < 512; i += 128) {
                int row = i >> 3, ch = i & 7;
                *reinterpret_cast<uint4*>(smem + SM_B + p * 8192 + row * 128 +
                                          ((ch ^ (row & 7)) << 4)) = src[i];
            }
        }
        __syncthreads();

        int brow = (lane & 7);          // filled per-n8 below
        int bhi = (lane >> 3) & 1;

#pragma unroll 2
        for (int n8 = 0; n8 < 8; n8++) {
            float acc0[4] = {0, 0, 0, 0};
            float acc1[4] = {0, 0, 0, 0};
            int row = n8 * 8 + brow;
            int rsw = row & 7;
#pragma unroll
            for (int bp = 0; bp < 2; bp++) {
#pragma unroll
                for (int k = 0; k < 4; k++) {
                    uint32_t bf[2];
                    int ch = (2 * k + bhi) ^ rsw;
                    ldsm_x2(bf, sb + SM_B + bp * 8192 + row * 128 + ch * 16);
                    mma16816(acc0, af[0][0][k], bf);
                    mma16816(acc1, af[0][1][k], bf);
                    mma16816(acc0, af[1][0][k], bf);
                    mma16816(acc1, af[1][1][k], bf);
                }
            }
            // epilogue: acc element e -> row +8*(e>>1), col +(e&1)
            int ncol = tile * 64 + n8 * 8 + 2 * (lane & 3);
            float s0 = scn[ncol], s1 = scn[ncol + 1];
            {
                float v;
                v = acc0[0] - s0; if (v > best[0]) { best[0] = v; idx[0] = ncol; }
                v = acc0[1] - s1; if (v > best[0]) { best[0] = v; idx[0] = ncol + 1; }
                v = acc0[2] - s0; if (v > best[1]) { best[1] = v; idx[1] = ncol; }
                v = acc0[3] - s1; if (v > best[1]) { best[1] = v; idx[1] = ncol + 1; }
                v = acc1[0] - s0; if (v > best[2]) { best[2] = v; idx[2] = ncol; }
                v = acc1[1] - s1; if (v > best[2]) { best[2] = v; idx[2] = ncol + 1; }
                v = acc1[2] - s0; if (v > best[3]) { best[3] = v; idx[3] = ncol; }
                v = acc1[3] - s1; if (v > best[3]) { best[3] = v; idx[3] = ncol + 1; }
            }
        }
    }

    // quad reduce (lanes sharing l>>2 hold different column sets)
#pragma unroll
    for (int slot = 0; slot < 4; slot++) {
#pragma unroll
        for (int off = 1; off <= 2; off <<= 1) {
            float ob = __shfl_xor_sync(0xffffffffu, best[slot], off);
            int oi = __shfl_xor_sync(0xffffffffu, idx[slot], off);
            if (ob > best[slot] || (ob == best[slot] && oi < idx[slot])) {
                best[slot] = ob; idx[slot] = oi;
            }
        }
    }
    // after reduce, all 4 lanes of a quad agree; slot -> row mapping:
    // row = wid*32 + (slot>>1)*16 + (slot&1)*8 + (lane>>2)
    float errsum = 0.f;
#pragma unroll
    for (int slot = 0; slot < 4; slot++) {
        int row = wid * 32 + (slot >> 1) * 16 + (slot & 1) * 8 + (lane >> 2);
        int n = cta * M_TILE + row;
        // codeword gather: all 4 lanes of the quad cooperate (16B each x4)
        const float4* c = reinterpret_cast<const float4*>(g_c + (size_t)idx[slot] * NK);
        float4* o = reinterpret_cast<float4*>(out + (size_t)n * NK);
#pragma unroll
        for (int j = lane & 3; j < 16; j += 4) o[j] = c[j];
        if ((lane & 3) == 0) {
            float err = fmaxf(g_vn[n] - 2.0f * best[slot], 0.0f);
            out[OFF_Z + n] = (float)idx[slot];
            out[OFF_ERR + n] = err;
            errsum += err;
        }
    }
    // deterministic errs2 reduction
#pragma unroll
    for (int o = 16; o; o >>= 1) errsum += __shfl_xor_sync(0xffffffffu, errsum, o);
    float* red = reinterpret_cast<float*>(smem + SM_RED);
    if (lane == 0) red[wid] = errsum;
    __syncthreads();
    if (tid == 0) g_partial[cta] = (red[0] + red[1]) + (red[2] + red[3]);
}

// ---------------------------------------------------------------------------
// Kernel 4: finalize scalars — parallel deterministic tree reduction.
// ---------------------------------------------------------------------------
__global__ void __launch_bounds__(512) vq_finalize(float* __restrict__ out) {
    __shared__ float red[512];
    int tid = threadIdx.x;
    red[tid] = g_partial[tid];
    __syncthreads();
#pragma unroll
    for (int off = 256; off > 0; off >>= 1) {
        if (tid < off) red[tid] += red[tid + off];
        __syncthreads();
    }
    if (tid == 0) {
        out[OFF_COMMIT] = red[0] * (1.0f / (float)NVEC);
        out[OFF_CB] = 0.0f;   // l_codebook is identically 0 in forward value
    }
}

extern "C" void kernel_launch(void* const* d_in, const int* in_sizes, int n_in,
                              void* d_out, int out_size) {
    const float* vecs    = (const float*)d_in[0];
    const float* c_sum   = (const float*)d_in[1];
    const float* c_count = (const float*)d_in[2];
    float* out = (float*)d_out;

    cudaFuncSetAttribute(vq_mma, cudaFuncAttributeMaxDynamicSharedMemorySize, SM_TOT);

    vq_prep_code<<<128, 128>>>(c_sum, c_count);
    vq_prep_vec<<<NVEC / 128, 128>>>(vecs);
    vq_mma<<<NCTA, 128, SM_TOT>>>(out);
    vq_finalize<<<1, 512>>>(out);
}

// round 7
// speedup vs baseline: 2.9272x; 1.3937x over previous
#include <cuda_runtime.h>
#include <cuda_fp16.h>
#include <cstdint>

#define NS 512
#define NK 64
#define NVEC 65536
#define M_TILE 128
#define NCTA (NVEC / M_TILE)      /* 512 */

#define OFF_Z      (NVEC*NK)
#define OFF_COMMIT (OFF_Z + NVEC)
#define OFF_CB     (OFF_COMMIT + 1)
#define OFF_ERR    (OFF_CB + 1)

/* dynamic smem layout */
#define SM_A    0           /* 2 planes * 128 rows * 128B = 32768 */
#define SM_B    32768       /* double buffer: 2 * (2 planes * 64 rows * 128B) = 32768 */
#define SM_SCN  65536       /* 512 * 4 = 2048 */
#define SM_VN   67584       /* 128 * 4 = 512 */
#define SM_RED  68096       /* 4 * 4 */
#define SM_TOT  68224

__device__ float  g_c[NS * NK];          // fp32 codebook
__device__ float  g_cnh[NS];             // 0.5*||c||^2
__device__ __half g_ch[2][NS * NK];      // codebook fp16 planes (h0, h1)
__device__ float  g_partial[NCTA];
__device__ int    g_done;

__device__ __forceinline__ uint32_t smem_u32(const void* p) {
    uint32_t a;
    asm("{ .reg .u64 t; cvta.to.shared.u64 t, %1; cvt.u32.u64 %0, t; }" : "=r"(a) : "l"(p));
    return a;
}
__device__ __forceinline__ void ldsm_x4(uint32_t* r, uint32_t a) {
    asm volatile("ldmatrix.sync.aligned.m8n8.x4.shared.b16 {%0,%1,%2,%3}, [%4];"
                 : "=r"(r[0]), "=r"(r[1]), "=r"(r[2]), "=r"(r[3]) : "r"(a));
}
__device__ __forceinline__ void ldsm_x2(uint32_t* r, uint32_t a) {
    asm volatile("ldmatrix.sync.aligned.m8n8.x2.shared.b16 {%0,%1}, [%2];"
                 : "=r"(r[0]), "=r"(r[1]) : "r"(a));
}
__device__ __forceinline__ void mma16816(float* c, const uint32_t* a, const uint32_t* b) {
    asm volatile("mma.sync.aligned.m16n8k16.row.col.f32.f16.f16.f32 "
                 "{%0,%1,%2,%3}, {%4,%5,%6,%7}, {%8,%9}, {%0,%1,%2,%3};"
                 : "+f"(c[0]), "+f"(c[1]), "+f"(c[2]), "+f"(c[3])
                 : "r"(a[0]), "r"(a[1]), "r"(a[2]), "r"(a[3]), "r"(b[0]), "r"(b[1]));
}
__device__ __forceinline__ void cpa16(uint32_t dst, const void* src) {
    asm volatile("cp.async.cg.shared.global [%0], [%1], 16;" :: "r"(dst), "l"(src));
}
#define CPA_COMMIT() asm volatile("cp.async.commit_group;" ::: "memory")
#define CPA_WAIT(n)  asm volatile("cp.async.wait_group %0;" :: "n"(n) : "memory")

__device__ __forceinline__ void hsplit(float x, __half& h0, __half& h1) {
    h0 = __float2half_rn(x);
    h1 = __float2half_rn(x - __half2float(h0));
}

// ---------------------------------------------------------------------------
// Kernel 1: codebook -> fp32 + half-norms + fp16 planes; reset done counter.
// ---------------------------------------------------------------------------
__global__ void __launch_bounds__(128) vq_prep_code(const float* __restrict__ c_sum,
                                                    const float* __restrict__ c_count) {
    if (blockIdx.x == 0 && threadIdx.x == 0) g_done = 0;
    int warp = (blockIdx.x * blockDim.x + threadIdx.x) >> 5;
    int lane = threadIdx.x & 31;
    if (warp >= NS) return;
    float inv = 1.0f / fmaxf(c_count[warp], 0.01f);
    float a = c_sum[warp * NK + lane] * inv;
    float b = c_sum[warp * NK + 32 + lane] * inv;
    g_c[warp * NK + lane] = a;
    g_c[warp * NK + 32 + lane] = b;
    __half h0, h1;
    hsplit(a, h0, h1);
    g_ch[0][warp * NK + lane] = h0;
    g_ch[1][warp * NK + lane] = h1;
    hsplit(b, h0, h1);
    g_ch[0][warp * NK + 32 + lane] = h0;
    g_ch[1][warp * NK + 32 + lane] = h1;
    float nh = a * a + b * b;
#pragma unroll
    for (int o = 16; o; o >>= 1) nh += __shfl_xor_sync(0xffffffffu, nh, o);
    if (lane == 0) g_cnh[warp] = 0.5f * nh;
}

// ---------------------------------------------------------------------------
// Kernel 2: fused convert + mma.sync search + outputs + fused finalize.
// CTA = 128 vectors vs 512 codes; 4 warps; 3-term fp16 split
// (a0b0 + a1b0 + a0b1), cp.async double-buffered B tiles.
// ---------------------------------------------------------------------------
__global__ void __launch_bounds__(128) vq_mma(const float* __restrict__ vecs,
                                              float* __restrict__ out) {
    extern __shared__ __align__(128) char smem[];
    uint32_t sb = smem_u32(smem);
    int tid = threadIdx.x;
    int wid = tid >> 5;
    int lane = tid & 31;
    int cta = blockIdx.x;

    // codebook half-norms -> smem
    for (int i = tid; i < NS; i += 128)
        reinterpret_cast<float*>(smem + SM_SCN)[i] = g_cnh[i];

    // fused A conversion: thread t owns vector row t
    {
        const float4* src = reinterpret_cast<const float4*>(vecs + ((size_t)cta * M_TILE + tid) * NK);
        float vn = 0.f;
        int rsw = tid & 7;
#pragma unroll
        for (int ch = 0; ch < 8; ch++) {            // 8 halves per 16B chunk
            float4 q0 = src[2 * ch], q1 = src[2 * ch + 1];
            float x[8] = {q0.x, q0.y, q0.z, q0.w, q1.x, q1.y, q1.z, q1.w};
            union { uint4 u; __half2 h[4]; } p0, p1;
#pragma unroll
            for (int j = 0; j < 4; j++) {
                __half a0, a1, b0, b1;
                hsplit(x[2 * j], a0, a1);
                hsplit(x[2 * j + 1], b0, b1);
                p0.h[j] = __halves2half2(a0, b0);
                p1.h[j] = __halves2half2(a1, b1);
                vn += x[2 * j] * x[2 * j] + x[2 * j + 1] * x[2 * j + 1];
            }
            uint32_t off = tid * 128 + ((ch ^ rsw) << 4);
            *reinterpret_cast<uint4*>(smem + SM_A + off) = p0.u;
            *reinterpret_cast<uint4*>(smem + SM_A + 16384 + off) = p1.u;
        }
        reinterpret_cast<float*>(smem + SM_VN)[tid] = vn;
    }

    // prefetch B tile 0 (both planes) into buffer 0
    auto loadB = [&](int tile, int buf) {
#pragma unroll
        for (int j = 0; j < 8; j++) {
            int i = tid + 128 * j;            // 1024 chunks of 16B
            int row = i >> 3, ch = i & 7;     // row 0..127 across 2 planes
            int p = row >> 6, r = row & 63;
            const __half* src = g_ch[p] + ((size_t)tile * 64 + r) * NK + ch * 8;
            cpa16(sb + SM_B + buf * 16384 + p * 8192 + r * 128 + (((ch ^ (r & 7))) << 4), src);
        }
    };
    loadB(0, 0);
    CPA_COMMIT();
    __syncthreads();

    // register-resident A fragments: [plane][mtile][kstep][4]
    uint32_t af[2][2][4][4];
    {
        int r = lane & 15;
        int hi = lane >> 4;
#pragma unroll
        for (int p = 0; p < 2; p++)
#pragma unroll
            for (int mt = 0; mt < 2; mt++) {
                int row = wid * 32 + mt * 16 + r;
#pragma unroll
                for (int k = 0; k < 4; k++) {
                    int ch = (2 * k + hi) ^ (row & 7);
                    ldsm_x4(af[p][mt][k], sb + SM_A + p * 16384 + row * 128 + ch * 16);
                }
            }
    }

    const float* scn = reinterpret_cast<const float*>(smem + SM_SCN);
    float best[4] = {-3.4e38f, -3.4e38f, -3.4e38f, -3.4e38f};
    int idx[4] = {0, 0, 0, 0};
    int bhi = (lane >> 3) & 1;

    for (int tile = 0; tile < 8; tile++) {
        if (tile < 7) { loadB(tile + 1, (tile + 1) & 1); CPA_COMMIT(); }
        if (tile < 7) { CPA_WAIT(1); } else { CPA_WAIT(0); }
        __syncthreads();
        uint32_t bbase = sb + SM_B + (tile & 1) * 16384;

#pragma unroll 2
        for (int n8 = 0; n8 < 8; n8++) {
            float acc0[4] = {0, 0, 0, 0};
            float acc1[4] = {0, 0, 0, 0};
            int row = n8 * 8 + (lane & 7);
            int rsw = row & 7;
#pragma unroll
            for (int k = 0; k < 4; k++) {       // B plane 0: a0 and a1 terms
                uint32_t bf[2];
                ldsm_x2(bf, bbase + row * 128 + (((2 * k + bhi) ^ rsw) << 4));
                mma16816(acc0, af[0][0][k], bf);
                mma16816(acc1, af[0][1][k], bf);
                mma16816(acc0, af[1][0][k], bf);
                mma16816(acc1, af[1][1][k], bf);
            }
#pragma unroll
            for (int k = 0; k < 4; k++) {       // B plane 1: a0 term only
                uint32_t bf[2];
                ldsm_x2(bf, bbase + 8192 + row * 128 + (((2 * k + bhi) ^ rsw) << 4));
                mma16816(acc0, af[0][0][k], bf);
                mma16816(acc1, af[0][1][k], bf);
            }
            int ncol = tile * 64 + n8 * 8 + 2 * (lane & 3);
            float s0 = scn[ncol], s1 = scn[ncol + 1];
            float v;
            v = acc0[0] - s0; if (v > best[0]) { best[0] = v; idx[0] = ncol; }
            v = acc0[1] - s1; if (v > best[0]) { best[0] = v; idx[0] = ncol + 1; }
            v = acc0[2] - s0; if (v > best[1]) { best[1] = v; idx[1] = ncol; }
            v = acc0[3] - s1; if (v > best[1]) { best[1] = v; idx[1] = ncol + 1; }
            v = acc1[0] - s0; if (v > best[2]) { best[2] = v; idx[2] = ncol; }
            v = acc1[1] - s1; if (v > best[2]) { best[2] = v; idx[2] = ncol + 1; }
            v = acc1[2] - s0; if (v > best[3]) { best[3] = v; idx[3] = ncol; }
            v = acc1[3] - s1; if (v > best[3]) { best[3] = v; idx[3] = ncol + 1; }
        }
        __syncthreads();   // all warps done with this buffer before re-issue
    }

    // quad reduce (tie -> lower index)
#pragma unroll
    for (int slot = 0; slot < 4; slot++) {
#pragma unroll
        for (int off = 1; off <= 2; off <<= 1) {
            float ob = __shfl_xor_sync(0xffffffffu, best[slot], off);
            int oi = __shfl_xor_sync(0xffffffffu, idx[slot], off);
            if (ob > best[slot] || (ob == best[slot] && oi < idx[slot])) {
                best[slot] = ob; idx[slot] = oi;
            }
        }
    }

    const float* svn = reinterpret_cast<const float*>(smem + SM_VN);
    float errsum = 0.f;
#pragma unroll
    for (int slot = 0; slot < 4; slot++) {
        int row = wid * 32 + (slot >> 1) * 16 + (slot & 1) * 8 + (lane >> 2);
        int n = cta * M_TILE + row;
        const float4* c = reinterpret_cast<const float4*>(g_c + (size_t)idx[slot] * NK);
        float4* o = reinterpret_cast<float4*>(out + (size_t)n * NK);
#pragma unroll
        for (int j = lane & 3; j < 16; j += 4) o[j] = c[j];
        if ((lane & 3) == 0) {
            float err = fmaxf(svn[row] - 2.0f * best[slot], 0.0f);
            out[OFF_Z + n] = (float)idx[slot];
            out[OFF_ERR + n] = err;
            errsum += err;
        }
    }
#pragma unroll
    for (int o = 16; o; o >>= 1) errsum += __shfl_xor_sync(0xffffffffu, errsum, o);
    float* red = reinterpret_cast<float*>(smem + SM_RED);
    if (lane == 0) red[wid] = errsum;
    __syncthreads();
    if (tid == 0) g_partial[cta] = (red[0] + red[1]) + (red[2] + red[3]);

    // fused finalize: last CTA reduces all partials (fixed deterministic order)
    __shared__ int s_last;
    if (tid == 0) {
        __threadfence();
        s_last = (atomicAdd(&g_done, 1) == NCTA - 1);
    }
    __syncthreads();
    if (s_last) {
        __threadfence();
        float* fred = reinterpret_cast<float*>(smem + SM_A);   // reuse smem
        float v = g_partial[tid] + g_partial[tid + 128]
                + g_partial[tid + 256] + g_partial[tid + 384];
        fred[tid] = v;
        __syncthreads();
#pragma unroll
        for (int off = 64; off > 0; off >>= 1) {
            if (tid < off) fred[tid] += fred[tid + off];
            __syncthreads();
        }
        if (tid == 0) {
            out[OFF_COMMIT] = fred[0] * (1.0f / (float)NVEC);
            out[OFF_CB] = 0.0f;   // l_codebook is identically 0 in forward value
        }
    }
}

extern "C" void kernel_launch(void* const* d_in, const int* in_sizes, int n_in,
                              void* d_out, int out_size) {
    const float* vecs    = (const float*)d_in[0];
    const float* c_sum   = (const float*)d_in[1];
    const float* c_count = (const float*)d_in[2];
    float* out = (float*)d_out;

    cudaFuncSetAttribute(vq_mma, cudaFuncAttributeMaxDynamicSharedMemorySize, SM_TOT);

    vq_prep_code<<<128, 128>>>(c_sum, c_count);
    vq_mma<<<NCTA, 128, SM_TOT>>>(vecs, out);
}

// round 8
// speedup vs baseline: 3.0462x; 1.0407x over previous
#include <cuda_runtime.h>
#include <cuda_fp16.h>
#include <cstdint>

#define NS 512
#define NK 64
#define NVEC 65536
#define M_TILE 128
#define NCTA (NVEC / M_TILE)      /* 512 */

#define OFF_Z      (NVEC*NK)
#define OFF_COMMIT (OFF_Z + NVEC)
#define OFF_CB     (OFF_COMMIT + 1)
#define OFF_ERR    (OFF_CB + 1)

/* dynamic smem: A region [0,32768) is reused as the B double-buffer
   once A fragments are register-resident. */
#define SM_A    0           /* phase 1: 2 planes * 128 * 128B */
#define SM_B    0           /* phase 2: 2 stages * 16384 */
#define SM_SCN  32768       /* 512 * 4 */
#define SM_VN   34816       /* 128 * 4 */
#define SM_RED  35328       /* 16 */
#define SM_TOT  35360

__device__ float  g_c[NS * NK];          // fp32 codebook
__device__ float  g_cnh[NS];             // 0.5*||c||^2
__device__ __half g_ch[2][NS * NK];      // codebook fp16 planes (h0, h1)
__device__ float  g_partial[NCTA];
__device__ int    g_done;

__device__ __forceinline__ uint32_t smem_u32(const void* p) {
    uint32_t a;
    asm("{ .reg .u64 t; cvta.to.shared.u64 t, %1; cvt.u32.u64 %0, t; }" : "=r"(a) : "l"(p));
    return a;
}
__device__ __forceinline__ void ldsm_x4(uint32_t* r, uint32_t a) {
    asm volatile("ldmatrix.sync.aligned.m8n8.x4.shared.b16 {%0,%1,%2,%3}, [%4];"
                 : "=r"(r[0]), "=r"(r[1]), "=r"(r[2]), "=r"(r[3]) : "r"(a));
}
__device__ __forceinline__ void mma16816(float* c, const uint32_t* a, const uint32_t* b) {
    asm volatile("mma.sync.aligned.m16n8k16.row.col.f32.f16.f16.f32 "
                 "{%0,%1,%2,%3}, {%4,%5,%6,%7}, {%8,%9}, {%0,%1,%2,%3};"
                 : "+f"(c[0]), "+f"(c[1]), "+f"(c[2]), "+f"(c[3])
                 : "r"(a[0]), "r"(a[1]), "r"(a[2]), "r"(a[3]), "r"(b[0]), "r"(b[1]));
}
__device__ __forceinline__ void cpa16(uint32_t dst, const void* src) {
    asm volatile("cp.async.cg.shared.global [%0], [%1], 16;" :: "r"(dst), "l"(src));
}
#define CPA_COMMIT() asm volatile("cp.async.commit_group;" ::: "memory")
#define CPA_WAIT(n)  asm volatile("cp.async.wait_group %0;" :: "n"(n) : "memory")

__device__ __forceinline__ void hsplit(float x, __half& h0, __half& h1) {
    h0 = __float2half_rn(x);
    h1 = __float2half_rn(x - __half2float(h0));
}

// ---------------------------------------------------------------------------
// Kernel 1: codebook -> fp32 + half-norms + fp16 planes; reset done counter.
// ---------------------------------------------------------------------------
__global__ void __launch_bounds__(128) vq_prep_code(const float* __restrict__ c_sum,
                                                    const float* __restrict__ c_count) {
    if (blockIdx.x == 0 && threadIdx.x == 0) g_done = 0;
    int warp = (blockIdx.x * blockDim.x + threadIdx.x) >> 5;
    int lane = threadIdx.x & 31;
    if (warp >= NS) return;
    float inv = 1.0f / fmaxf(c_count[warp], 0.01f);
    float a = c_sum[warp * NK + lane] * inv;
    float b = c_sum[warp * NK + 32 + lane] * inv;
    g_c[warp * NK + lane] = a;
    g_c[warp * NK + 32 + lane] = b;
    __half h0, h1;
    hsplit(a, h0, h1);
    g_ch[0][warp * NK + lane] = h0;
    g_ch[1][warp * NK + lane] = h1;
    hsplit(b, h0, h1);
    g_ch[0][warp * NK + 32 + lane] = h0;
    g_ch[1][warp * NK + 32 + lane] = h1;
    float nh = a * a + b * b;
#pragma unroll
    for (int o = 16; o; o >>= 1) nh += __shfl_xor_sync(0xffffffffu, nh, o);
    if (lane == 0) g_cnh[warp] = 0.5f * nh;
}

// ---------------------------------------------------------------------------
// Kernel 2: fused convert + mma.sync search + outputs + fused finalize.
// 4 CTAs/SM (35KB smem), single wave; ldsm_x4 B, 4 acc chains/warp.
// ---------------------------------------------------------------------------
__global__ void __launch_bounds__(128, 4) vq_mma(const float* __restrict__ vecs,
                                                 float* __restrict__ out) {
    extern __shared__ __align__(128) char smem[];
    uint32_t sb = smem_u32(smem);
    int tid = threadIdx.x;
    int wid = tid >> 5;
    int lane = tid & 31;
    int cta = blockIdx.x;

    for (int i = tid; i < NS; i += 128)
        reinterpret_cast<float*>(smem + SM_SCN)[i] = g_cnh[i];

    // fused A conversion into smem (phase 1 use of the shared region)
    {
        const float4* src = reinterpret_cast<const float4*>(vecs + ((size_t)cta * M_TILE + tid) * NK);
        float vn = 0.f;
        int rsw = tid & 7;
#pragma unroll
        for (int ch = 0; ch < 8; ch++) {
            float4 q0 = src[2 * ch], q1 = src[2 * ch + 1];
            float x[8] = {q0.x, q0.y, q0.z, q0.w, q1.x, q1.y, q1.z, q1.w};
            union { uint4 u; __half2 h[4]; } p0, p1;
#pragma unroll
            for (int j = 0; j < 4; j++) {
                __half a0, a1, b0, b1;
                hsplit(x[2 * j], a0, a1);
                hsplit(x[2 * j + 1], b0, b1);
                p0.h[j] = __halves2half2(a0, b0);
                p1.h[j] = __halves2half2(a1, b1);
                vn += x[2 * j] * x[2 * j] + x[2 * j + 1] * x[2 * j + 1];
            }
            uint32_t off = tid * 128 + ((ch ^ rsw) << 4);
            *reinterpret_cast<uint4*>(smem + SM_A + off) = p0.u;
            *reinterpret_cast<uint4*>(smem + SM_A + 16384 + off) = p1.u;
        }
        reinterpret_cast<float*>(smem + SM_VN)[tid] = vn;
    }
    __syncthreads();

    // register-resident A fragments: [plane][mtile][kstep][4]
    uint32_t af[2][2][4][4];
    {
        int r = lane & 15;
        int hi = lane >> 4;
#pragma unroll
        for (int p = 0; p < 2; p++)
#pragma unroll
            for (int mt = 0; mt < 2; mt++) {
                int row = wid * 32 + mt * 16 + r;
#pragma unroll
                for (int k = 0; k < 4; k++) {
                    int ch = (2 * k + hi) ^ (row & 7);
                    ldsm_x4(af[p][mt][k], sb + SM_A + p * 16384 + row * 128 + ch * 16);
                }
            }
    }
    __syncthreads();   // everyone done reading A region; it becomes B buffers

    auto loadB = [&](int tile, int buf) {
#pragma unroll
        for (int j = 0; j < 8; j++) {
            int i = tid + 128 * j;
            int row = i >> 3, ch = i & 7;
            int p = row >> 6, r = row & 63;
            const __half* src = g_ch[p] + ((size_t)tile * 64 + r) * NK + ch * 8;
            cpa16(sb + SM_B + buf * 16384 + p * 8192 + r * 128 + (((ch ^ (r & 7))) << 4), src);
        }
    };
    loadB(0, 0);
    CPA_COMMIT();

    const float* scn = reinterpret_cast<const float*>(smem + SM_SCN);
    float best[4] = {-3.4e38f, -3.4e38f, -3.4e38f, -3.4e38f};
    int idx[4] = {0, 0, 0, 0};
    int brow_lo = (lane >> 4) << 3;   // +0 or +8 (nblock within pair)
    int kh = (lane >> 3) & 1;

    for (int tile = 0; tile < 8; tile++) {
        if (tile < 7) { loadB(tile + 1, (tile + 1) & 1); CPA_COMMIT(); CPA_WAIT(1); }
        else CPA_WAIT(0);
        __syncthreads();
        uint32_t bbase = sb + SM_B + (tile & 1) * 16384;

#pragma unroll
        for (int npair = 0; npair < 4; npair++) {
            float acc[2][2][4] = {};
            int row = npair * 16 + brow_lo + (lane & 7);
            int rsw = row & 7;
#pragma unroll
            for (int k = 0; k < 4; k++) {     // B plane 0: a0 + a1 terms
                uint32_t bf[4];
                ldsm_x4(bf, bbase + row * 128 + (((2 * k + kh) ^ rsw) << 4));
                mma16816(acc[0][0], af[0][0][k], bf + 0);
                mma16816(acc[0][1], af[0][0][k], bf + 2);
                mma16816(acc[1][0], af[0][1][k], bf + 0);
                mma16816(acc[1][1], af[0][1][k], bf + 2);
                mma16816(acc[0][0], af[1][0][k], bf + 0);
                mma16816(acc[0][1], af[1][0][k], bf + 2);
                mma16816(acc[1][0], af[1][1][k], bf + 0);
                mma16816(acc[1][1], af[1][1][k], bf + 2);
            }
#pragma unroll
            for (int k = 0; k < 4; k++) {     // B plane 1: a0 term only
                uint32_t bf[4];
                ldsm_x4(bf, bbase + 8192 + row * 128 + (((2 * k + kh) ^ rsw) << 4));
                mma16816(acc[0][0], af[0][0][k], bf + 0);
                mma16816(acc[0][1], af[0][0][k], bf + 2);
                mma16816(acc[1][0], af[0][1][k], bf + 0);
                mma16816(acc[1][1], af[0][1][k], bf + 2);
            }
#pragma unroll
            for (int nb = 0; nb < 2; nb++) {
                int ncol = tile * 64 + npair * 16 + nb * 8 + 2 * (lane & 3);
                float s0 = scn[ncol], s1 = scn[ncol + 1];
                float v;
                v = acc[0][nb][0] - s0; if (v > best[0]) { best[0] = v; idx[0] = ncol; }
                v = acc[0][nb][1] - s1; if (v > best[0]) { best[0] = v; idx[0] = ncol + 1; }
                v = acc[0][nb][2] - s0; if (v > best[1]) { best[1] = v; idx[1] = ncol; }
                v = acc[0][nb][3] - s1; if (v > best[1]) { best[1] = v; idx[1] = ncol + 1; }
                v = acc[1][nb][0] - s0; if (v > best[2]) { best[2] = v; idx[2] = ncol; }
                v = acc[1][nb][1] - s1; if (v > best[2]) { best[2] = v; idx[2] = ncol + 1; }
                v = acc[1][nb][2] - s0; if (v > best[3]) { best[3] = v; idx[3] = ncol; }
                v = acc[1][nb][3] - s1; if (v > best[3]) { best[3] = v; idx[3] = ncol + 1; }
            }
        }
        __syncthreads();
    }

    // quad reduce (tie -> lower index)
#pragma unroll
    for (int slot = 0; slot < 4; slot++) {
#pragma unroll
        for (int off = 1; off <= 2; off <<= 1) {
            float ob = __shfl_xor_sync(0xffffffffu, best[slot], off);
            int oi = __shfl_xor_sync(0xffffffffu, idx[slot], off);
            if (ob > best[slot] || (ob == best[slot] && oi < idx[slot])) {
                best[slot] = ob; idx[slot] = oi;
            }
        }
    }

    const float* svn = reinterpret_cast<const float*>(smem + SM_VN);
    float errsum = 0.f;
#pragma unroll
    for (int slot = 0; slot < 4; slot++) {
        int row = wid * 32 + (slot >> 1) * 16 + (slot & 1) * 8 + (lane >> 2);
        int n = cta * M_TILE + row;
        const float4* c = reinterpret_cast<const float4*>(g_c + (size_t)idx[slot] * NK);
        float4* o = reinterpret_cast<float4*>(out + (size_t)n * NK);
#pragma unroll
        for (int j = lane & 3; j < 16; j += 4) o[j] = c[j];
        if ((lane & 3) == 0) {
            float err = fmaxf(svn[row] - 2.0f * best[slot], 0.0f);
            out[OFF_Z + n] = (float)idx[slot];
            out[OFF_ERR + n] = err;
            errsum += err;
        }
    }
#pragma unroll
    for (int o = 16; o; o >>= 1) errsum += __shfl_xor_sync(0xffffffffu, errsum, o);
    float* red = reinterpret_cast<float*>(smem + SM_RED);
    if (lane == 0) red[wid] = errsum;
    __syncthreads();
    if (tid == 0) g_partial[cta] = (red[0] + red[1]) + (red[2] + red[3]);

    // fused finalize: last CTA reduces all partials (fixed deterministic order)
    __shared__ int s_last;
    if (tid == 0) {
        __threadfence();
        s_last = (atomicAdd(&g_done, 1) == NCTA - 1);
    }
    __syncthreads();
    if (s_last) {
        __threadfence();
        float* fred = reinterpret_cast<float*>(smem + SM_A);
        float v = g_partial[tid] + g_partial[tid + 128]
                + g_partial[tid + 256] + g_partial[tid + 384];
        fred[tid] = v;
        __syncthreads();
#pragma unroll
        for (int off = 64; off > 0; off >>= 1) {
            if (tid < off) fred[tid] += fred[tid + off];
            __syncthreads();
        }
        if (tid == 0) {
            out[OFF_COMMIT] = fred[0] * (1.0f / (float)NVEC);
            out[OFF_CB] = 0.0f;   // l_codebook is identically 0 in forward value
        }
    }
}

extern "C" void kernel_launch(void* const* d_in, const int* in_sizes, int n_in,
                              void* d_out, int out_size) {
    const float* vecs    = (const float*)d_in[0];
    const float* c_sum   = (const float*)d_in[1];
    const float* c_count = (const float*)d_in[2];
    float* out = (float*)d_out;

    cudaFuncSetAttribute(vq_mma, cudaFuncAttributeMaxDynamicSharedMemorySize, SM_TOT);

    vq_prep_code<<<128, 128>>>(c_sum, c_count);
    vq_mma<<<NCTA, 128, SM_TOT>>>(vecs, out);
}

// round 9
// speedup vs baseline: 3.1876x; 1.0464x over previous
#include <cuda_runtime.h>
#include <cuda_fp16.h>
#include <cstdint>

#define NS 512
#define NK 64
#define NVEC 65536
#define M_TILE 128
#define NCTA (NVEC / M_TILE)      /* 512 */
#define NTHR 256

#define OFF_Z      (NVEC*NK)
#define OFF_COMMIT (OFF_Z + NVEC)
#define OFF_CB     (OFF_COMMIT + 1)
#define OFF_ERR    (OFF_CB + 1)

/* dynamic smem: A region [0,32768) reused as B double-buffer after
   A fragments are register-resident. */
#define SM_A    0
#define SM_B    0
#define SM_SCN  32768       /* 512*4 */
#define SM_VN   34816       /* 128*4 */
#define SM_RED  35328       /* 8*4 */
#define SM_TOT  35392

__device__ float  g_c[NS * NK];
__device__ float  g_cnh[NS];
__device__ __half g_ch[2][NS * NK];      // codebook fp16 planes (h0, h1)
__device__ float  g_partial[NCTA];
__device__ int    g_done;

__device__ __forceinline__ uint32_t smem_u32(const void* p) {
    uint32_t a;
    asm("{ .reg .u64 t; cvta.to.shared.u64 t, %1; cvt.u32.u64 %0, t; }" : "=r"(a) : "l"(p));
    return a;
}
__device__ __forceinline__ void ldsm_x4(uint32_t* r, uint32_t a) {
    asm volatile("ldmatrix.sync.aligned.m8n8.x4.shared.b16 {%0,%1,%2,%3}, [%4];"
                 : "=r"(r[0]), "=r"(r[1]), "=r"(r[2]), "=r"(r[3]) : "r"(a));
}
__device__ __forceinline__ void mma16816(float* c, const uint32_t* a, const uint32_t* b) {
    asm volatile("mma.sync.aligned.m16n8k16.row.col.f32.f16.f16.f32 "
                 "{%0,%1,%2,%3}, {%4,%5,%6,%7}, {%8,%9}, {%0,%1,%2,%3};"
                 : "+f"(c[0]), "+f"(c[1]), "+f"(c[2]), "+f"(c[3])
                 : "r"(a[0]), "r"(a[1]), "r"(a[2]), "r"(a[3]), "r"(b[0]), "r"(b[1]));
}
__device__ __forceinline__ void cpa16(uint32_t dst, const void* src) {
    asm volatile("cp.async.cg.shared.global [%0], [%1], 16;" :: "r"(dst), "l"(src));
}
#define CPA_COMMIT() asm volatile("cp.async.commit_group;" ::: "memory")
#define CPA_WAIT(n)  asm volatile("cp.async.wait_group %0;" :: "n"(n) : "memory")

__device__ __forceinline__ void hsplit(float x, __half& h0, __half& h1) {
    h0 = __float2half_rn(x);
    h1 = __float2half_rn(x - __half2float(h0));
}

// ---------------------------------------------------------------------------
// Kernel 1: codebook -> fp32 + half-norms + fp16 planes; reset done counter.
// ---------------------------------------------------------------------------
__global__ void __launch_bounds__(128) vq_prep_code(const float* __restrict__ c_sum,
                                                    const float* __restrict__ c_count) {
    if (blockIdx.x == 0 && threadIdx.x == 0) g_done = 0;
    int warp = (blockIdx.x * blockDim.x + threadIdx.x) >> 5;
    int lane = threadIdx.x & 31;
    if (warp >= NS) return;
    float inv = 1.0f / fmaxf(c_count[warp], 0.01f);
    float a = c_sum[warp * NK + lane] * inv;
    float b = c_sum[warp * NK + 32 + lane] * inv;
    g_c[warp * NK + lane] = a;
    g_c[warp * NK + 32 + lane] = b;
    __half h0, h1;
    hsplit(a, h0, h1);
    g_ch[0][warp * NK + lane] = h0;
    g_ch[1][warp * NK + lane] = h1;
    hsplit(b, h0, h1);
    g_ch[0][warp * NK + 32 + lane] = h0;
    g_ch[1][warp * NK + 32 + lane] = h1;
    float nh = a * a + b * b;
#pragma unroll
    for (int o = 16; o; o >>= 1) nh += __shfl_xor_sync(0xffffffffu, nh, o);
    if (lane == 0) g_cnh[warp] = 0.5f * nh;
}

// ---------------------------------------------------------------------------
// Kernel 2: 256 threads, 8 warps, each warp owns 16 rows of the 128-vector
// tile. 3 CTAs/SM -> 24 warps/SM for HMMA latency hiding.
// ---------------------------------------------------------------------------
__global__ void __launch_bounds__(NTHR, 3) vq_mma(const float* __restrict__ vecs,
                                                  float* __restrict__ out) {
    extern __shared__ __align__(128) char smem[];
    uint32_t sb = smem_u32(smem);
    int tid = threadIdx.x;
    int wid = tid >> 5;
    int lane = tid & 31;
    int cta = blockIdx.x;

    for (int i = tid; i < NS; i += NTHR)
        reinterpret_cast<float*>(smem + SM_SCN)[i] = g_cnh[i];

    // fused A conversion: thread pair (2t, 2t+1) owns vector row t (half each)
    {
        int row = tid >> 1;
        int half = tid & 1;
        const float4* src = reinterpret_cast<const float4*>(
            vecs + ((size_t)cta * M_TILE + row) * NK) + half * 8;
        float vn = 0.f;
        int rsw = row & 7;
#pragma unroll
        for (int c = 0; c < 4; c++) {               // 4 chunks of 8 halves
            int ch = half * 4 + c;
            float4 q0 = src[2 * c], q1 = src[2 * c + 1];
            float x[8] = {q0.x, q0.y, q0.z, q0.w, q1.x, q1.y, q1.z, q1.w};
            union { uint4 u; __half2 h[4]; } p0, p1;
#pragma unroll
            for (int j = 0; j < 4; j++) {
                __half a0, a1, b0, b1;
                hsplit(x[2 * j], a0, a1);
                hsplit(x[2 * j + 1], b0, b1);
                p0.h[j] = __halves2half2(a0, b0);
                p1.h[j] = __halves2half2(a1, b1);
                vn += x[2 * j] * x[2 * j] + x[2 * j + 1] * x[2 * j + 1];
            }
            uint32_t off = row * 128 + ((ch ^ rsw) << 4);
            *reinterpret_cast<uint4*>(smem + SM_A + off) = p0.u;
            *reinterpret_cast<uint4*>(smem + SM_A + 16384 + off) = p1.u;
        }
        vn += __shfl_xor_sync(0xffffffffu, vn, 1);
        if (half == 0) reinterpret_cast<float*>(smem + SM_VN)[row] = vn;
    }
    __syncthreads();

    // register-resident A fragments: [plane][kstep][4] (warp owns 16 rows)
    uint32_t af[2][4][4];
    {
        int r = lane & 15;
        int hi = lane >> 4;
#pragma unroll
        for (int p = 0; p < 2; p++) {
            int row = wid * 16 + r;
#pragma unroll
            for (int k = 0; k < 4; k++) {
                int ch = (2 * k + hi) ^ (row & 7);
                ldsm_x4(af[p][k], sb + SM_A + p * 16384 + row * 128 + ch * 16);
            }
        }
    }
    __syncthreads();   // A region becomes B double-buffer

    auto loadB = [&](int tile, int buf) {
#pragma unroll
        for (int j = 0; j < 4; j++) {
            int i = tid + NTHR * j;
            int row = i >> 3, ch = i & 7;
            int p = row >> 6, r = row & 63;
            const __half* src = g_ch[p] + ((size_t)tile * 64 + r) * NK + ch * 8;
            cpa16(sb + SM_B + buf * 16384 + p * 8192 + r * 128 + (((ch ^ (r & 7))) << 4), src);
        }
    };
    loadB(0, 0);
    CPA_COMMIT();

    const float* scn = reinterpret_cast<const float*>(smem + SM_SCN);
    float best[2] = {-3.4e38f, -3.4e38f};
    int idx[2] = {0, 0};
    int brow_lo = (lane >> 4) << 3;
    int kh = (lane >> 3) & 1;

    for (int tile = 0; tile < 8; tile++) {
        if (tile < 7) { loadB(tile + 1, (tile + 1) & 1); CPA_COMMIT(); CPA_WAIT(1); }
        else CPA_WAIT(0);
        __syncthreads();
        uint32_t bbase = sb + SM_B + (tile & 1) * 16384;

#pragma unroll
        for (int npair = 0; npair < 4; npair++) {
            float acc[2][4] = {};            // [nblock][4]
            int row = npair * 16 + brow_lo + (lane & 7);
            int rsw = row & 7;
#pragma unroll
            for (int k = 0; k < 4; k++) {    // B plane 0: a0 + a1 terms
                uint32_t bf[4];
                ldsm_x4(bf, bbase + row * 128 + (((2 * k + kh) ^ rsw) << 4));
                mma16816(acc[0], af[0][k], bf + 0);
                mma16816(acc[1], af[0][k], bf + 2);
                mma16816(acc[0], af[1][k], bf + 0);
                mma16816(acc[1], af[1][k], bf + 2);
            }
#pragma unroll
            for (int k = 0; k < 4; k++) {    // B plane 1: a0 term only
                uint32_t bf[4];
                ldsm_x4(bf, bbase + 8192 + row * 128 + (((2 * k + kh) ^ rsw) << 4));
                mma16816(acc[0], af[0][k], bf + 0);
                mma16816(acc[1], af[0][k], bf + 2);
            }
#pragma unroll
            for (int nb = 0; nb < 2; nb++) {
                int ncol = tile * 64 + npair * 16 + nb * 8 + 2 * (lane & 3);
                float s0 = scn[ncol], s1 = scn[ncol + 1];
                float v;
                v = acc[nb][0] - s0; if (v > best[0]) { best[0] = v; idx[0] = ncol; }
                v = acc[nb][1] - s1; if (v > best[0]) { best[0] = v; idx[0] = ncol + 1; }
                v = acc[nb][2] - s0; if (v > best[1]) { best[1] = v; idx[1] = ncol; }
                v = acc[nb][3] - s1; if (v > best[1]) { best[1] = v; idx[1] = ncol + 1; }
            }
        }
        __syncthreads();
    }

    // quad reduce (tie -> lower index)
#pragma unroll
    for (int slot = 0; slot < 2; slot++) {
#pragma unroll
        for (int off = 1; off <= 2; off <<= 1) {
            float ob = __shfl_xor_sync(0xffffffffu, best[slot], off);
            int oi = __shfl_xor_sync(0xffffffffu, idx[slot], off);
            if (ob > best[slot] || (ob == best[slot] && oi < idx[slot])) {
                best[slot] = ob; idx[slot] = oi;
            }
        }
    }

    const float* svn = reinterpret_cast<const float*>(smem + SM_VN);
    float errsum = 0.f;
#pragma unroll
    for (int slot = 0; slot < 2; slot++) {
        int row = wid * 16 + slot * 8 + (lane >> 2);
        int n = cta * M_TILE + row;
        const float4* c = reinterpret_cast<const float4*>(g_c + (size_t)idx[slot] * NK);
        float4* o = reinterpret_cast<float4*>(out + (size_t)n * NK);
#pragma unroll
        for (int j = lane & 3; j < 16; j += 4) o[j] = c[j];
        if ((lane & 3) == 0) {
            float err = fmaxf(svn[row] - 2.0f * best[slot], 0.0f);
            out[OFF_Z + n] = (float)idx[slot];
            out[OFF_ERR + n] = err;
            errsum += err;
        }
    }
#pragma unroll
    for (int o = 16; o; o >>= 1) errsum += __shfl_xor_sync(0xffffffffu, errsum, o);
    float* red = reinterpret_cast<float*>(smem + SM_RED);
    if (lane == 0) red[wid] = errsum;
    __syncthreads();
    if (tid == 0)
        g_partial[cta] = ((red[0] + red[1]) + (red[2] + red[3]))
                       + ((red[4] + red[5]) + (red[6] + red[7]));

    // fused finalize: last CTA reduces all partials (fixed deterministic order)
    __shared__ int s_last;
    if (tid == 0) {
        __threadfence();
        s_last = (atomicAdd(&g_done, 1) == NCTA - 1);
    }
    __syncthreads();
    if (s_last) {
        __threadfence();
        float* fred = reinterpret_cast<float*>(smem + SM_A);
        float v = g_partial[tid] + g_partial[tid + 256];
        fred[tid] = v;
        __syncthreads();
#pragma unroll
        for (int off = 128; off > 0; off >>= 1) {
            if (tid < off) fred[tid] += fred[tid + off];
            __syncthreads();
        }
        if (tid == 0) {
            out[OFF_COMMIT] = fred[0] * (1.0f / (float)NVEC);
            out[OFF_CB] = 0.0f;   // l_codebook is identically 0 in forward value
        }
    }
}

extern "C" void kernel_launch(void* const* d_in, const int* in_sizes, int n_in,
                              void* d_out, int out_size) {
    const float* vecs    = (const float*)d_in[0];
    const float* c_sum   = (const float*)d_in[1];
    const float* c_count = (const float*)d_in[2];
    float* out = (float*)d_out;

    cudaFuncSetAttribute(vq_mma, cudaFuncAttributeMaxDynamicSharedMemorySize, SM_TOT);

    vq_prep_code<<<128, 128>>>(c_sum, c_count);
    vq_mma<<<NCTA, NTHR, SM_TOT>>>(vecs, out);
}

// round 10
// speedup vs baseline: 3.1897x; 1.0006x over previous
#include <cuda_runtime.h>
#include <cuda_fp16.h>
#include <cstdint>

#define NS 512
#define NK 64
#define NVEC 65536
#define M_TILE 256
#define NCTA (NVEC / M_TILE)      /* 256 */
#define NTHR 256

#define OFF_Z      (NVEC*NK)
#define OFF_COMMIT (OFF_Z + NVEC)
#define OFF_CB     (OFF_COMMIT + 1)
#define OFF_ERR    (OFF_CB + 1)

/* dynamic smem: A region [0,65536) (2 planes * 256 rows * 128B) is reused
   as the 2x16KB B double-buffer after A fragments go register-resident. */
#define SM_A    0
#define SM_B    0
#define SM_SCN  65536       /* 512*4 */
#define SM_VN   67584       /* 256*4 */
#define SM_RED  68608       /* 8*4 */
#define SM_TOT  68672

__device__ float  g_c[NS * NK];
__device__ float  g_cnh[NS];
__device__ __half g_ch[2][NS * NK];      // codebook fp16 planes (h0, h1)
__device__ float  g_partial[NCTA];
__device__ int    g_done;

__device__ __forceinline__ uint32_t smem_u32(const void* p) {
    uint32_t a;
    asm("{ .reg .u64 t; cvta.to.shared.u64 t, %1; cvt.u32.u64 %0, t; }" : "=r"(a) : "l"(p));
    return a;
}
__device__ __forceinline__ void ldsm_x4(uint32_t* r, uint32_t a) {
    asm volatile("ldmatrix.sync.aligned.m8n8.x4.shared.b16 {%0,%1,%2,%3}, [%4];"
                 : "=r"(r[0]), "=r"(r[1]), "=r"(r[2]), "=r"(r[3]) : "r"(a));
}
__device__ __forceinline__ void mma16816(float* c, const uint32_t* a, const uint32_t* b) {
    asm volatile("mma.sync.aligned.m16n8k16.row.col.f32.f16.f16.f32 "
                 "{%0,%1,%2,%3}, {%4,%5,%6,%7}, {%8,%9}, {%0,%1,%2,%3};"
                 : "+f"(c[0]), "+f"(c[1]), "+f"(c[2]), "+f"(c[3])
                 : "r"(a[0]), "r"(a[1]), "r"(a[2]), "r"(a[3]), "r"(b[0]), "r"(b[1]));
}
__device__ __forceinline__ void cpa16(uint32_t dst, const void* src) {
    asm volatile("cp.async.cg.shared.global [%0], [%1], 16;" :: "r"(dst), "l"(src));
}
#define CPA_COMMIT() asm volatile("cp.async.commit_group;" ::: "memory")
#define CPA_WAIT(n)  asm volatile("cp.async.wait_group %0;" :: "n"(n) : "memory")

__device__ __forceinline__ void hsplit(float x, __half& h0, __half& h1) {
    h0 = __float2half_rn(x);
    h1 = __float2half_rn(x - __half2float(h0));
}

// ---------------------------------------------------------------------------
// Kernel 1: codebook -> fp32 + half-norms + fp16 planes; reset done counter.
// ---------------------------------------------------------------------------
__global__ void __launch_bounds__(128) vq_prep_code(const float* __restrict__ c_sum,
                                                    const float* __restrict__ c_count) {
    if (blockIdx.x == 0 && threadIdx.x == 0) g_done = 0;
    int warp = (blockIdx.x * blockDim.x + threadIdx.x) >> 5;
    int lane = threadIdx.x & 31;
    if (warp >= NS) return;
    float inv = 1.0f / fmaxf(c_count[warp], 0.01f);
    float a = c_sum[warp * NK + lane] * inv;
    float b = c_sum[warp * NK + 32 + lane] * inv;
    g_c[warp * NK + lane] = a;
    g_c[warp * NK + 32 + lane] = b;
    __half h0, h1;
    hsplit(a, h0, h1);
    g_ch[0][warp * NK + lane] = h0;
    g_ch[1][warp * NK + lane] = h1;
    hsplit(b, h0, h1);
    g_ch[0][warp * NK + 32 + lane] = h0;
    g_ch[1][warp * NK + 32 + lane] = h1;
    float nh = a * a + b * b;
#pragma unroll
    for (int o = 16; o; o >>= 1) nh += __shfl_xor_sync(0xffffffffu, nh, o);
    if (lane == 0) g_cnh[warp] = 0.5f * nh;
}

// ---------------------------------------------------------------------------
// Kernel 2: 256 threads, 8 warps, each warp owns 32 rows (2 mtiles) of the
// 256-vector tile -> 6:1 HMMA:LDSM ratio; 2 CTAs/SM.
// ---------------------------------------------------------------------------
__global__ void __launch_bounds__(NTHR, 2) vq_mma(const float* __restrict__ vecs,
                                                  float* __restrict__ out) {
    extern __shared__ __align__(128) char smem[];
    uint32_t sb = smem_u32(smem);
    int tid = threadIdx.x;
    int wid = tid >> 5;
    int lane = tid & 31;
    int cta = blockIdx.x;

    for (int i = tid; i < NS; i += NTHR)
        reinterpret_cast<float*>(smem + SM_SCN)[i] = g_cnh[i];

    // fused A conversion: thread t owns vector row t (256 rows)
    {
        const float4* src = reinterpret_cast<const float4*>(
            vecs + ((size_t)cta * M_TILE + tid) * NK);
        float vn = 0.f;
        int rsw = tid & 7;
#pragma unroll
        for (int ch = 0; ch < 8; ch++) {
            float4 q0 = src[2 * ch], q1 = src[2 * ch + 1];
            float x[8] = {q0.x, q0.y, q0.z, q0.w, q1.x, q1.y, q1.z, q1.w};
            union { uint4 u; __half2 h[4]; } p0, p1;
#pragma unroll
            for (int j = 0; j < 4; j++) {
                __half a0, a1, b0, b1;
                hsplit(x[2 * j], a0, a1);
                hsplit(x[2 * j + 1], b0, b1);
                p0.h[j] = __halves2half2(a0, b0);
                p1.h[j] = __halves2half2(a1, b1);
                vn += x[2 * j] * x[2 * j] + x[2 * j + 1] * x[2 * j + 1];
            }
            uint32_t off = tid * 128 + ((ch ^ rsw) << 4);
            *reinterpret_cast<uint4*>(smem + SM_A + off) = p0.u;
            *reinterpret_cast<uint4*>(smem + SM_A + 32768 + off) = p1.u;
        }
        reinterpret_cast<float*>(smem + SM_VN)[tid] = vn;
    }
    __syncthreads();

    // register-resident A fragments: [plane][mtile][kstep][4] (warp: 32 rows)
    uint32_t af[2][2][4][4];
    {
        int r = lane & 15;
        int hi = lane >> 4;
#pragma unroll
        for (int p = 0; p < 2; p++)
#pragma unroll
            for (int mt = 0; mt < 2; mt++) {
                int row = wid * 32 + mt * 16 + r;
#pragma unroll
                for (int k = 0; k < 4; k++) {
                    int ch = (2 * k + hi) ^ (row & 7);
                    ldsm_x4(af[p][mt][k], sb + SM_A + p * 32768 + row * 128 + ch * 16);
                }
            }
    }
    __syncthreads();   // A region becomes B double-buffer

    auto loadB = [&](int tile, int buf) {
#pragma unroll
        for (int j = 0; j < 4; j++) {
            int i = tid + NTHR * j;
            int row = i >> 3, ch = i & 7;
            int p = row >> 6, r = row & 63;
            const __half* src = g_ch[p] + ((size_t)tile * 64 + r) * NK + ch * 8;
            cpa16(sb + SM_B + buf * 16384 + p * 8192 + r * 128 + (((ch ^ (r & 7))) << 4), src);
        }
    };
    loadB(0, 0);
    CPA_COMMIT();

    const float* scn = reinterpret_cast<const float*>(smem + SM_SCN);
    float best[4] = {-3.4e38f, -3.4e38f, -3.4e38f, -3.4e38f};
    int idx[4] = {0, 0, 0, 0};
    int brow_lo = (lane >> 4) << 3;
    int kh = (lane >> 3) & 1;

    for (int tile = 0; tile < 8; tile++) {
        if (tile < 7) { loadB(tile + 1, (tile + 1) & 1); CPA_COMMIT(); CPA_WAIT(1); }
        else CPA_WAIT(0);
        __syncthreads();
        uint32_t bbase = sb + SM_B + (tile & 1) * 16384;

#pragma unroll
        for (int npair = 0; npair < 4; npair++) {
            float acc[2][2][4] = {};          // [mtile][nbhalf][4]
            int row = npair * 16 + brow_lo + (lane & 7);
            int rsw = row & 7;
#pragma unroll
            for (int k = 0; k < 4; k++) {     // B plane 0: a0 + a1 terms
                uint32_t bf[4];
                ldsm_x4(bf, bbase + row * 128 + (((2 * k + kh) ^ rsw) << 4));
#pragma unroll
                for (int mt = 0; mt < 2; mt++) {
                    mma16816(acc[mt][0], af[0][mt][k], bf + 0);
                    mma16816(acc[mt][1], af[0][mt][k], bf + 2);
                    mma16816(acc[mt][0], af[1][mt][k], bf + 0);
                    mma16816(acc[mt][1], af[1][mt][k], bf + 2);
                }
            }
#pragma unroll
            for (int k = 0; k < 4; k++) {     // B plane 1: a0 term only
                uint32_t bf[4];
                ldsm_x4(bf, bbase + 8192 + row * 128 + (((2 * k + kh) ^ rsw) << 4));
#pragma unroll
                for (int mt = 0; mt < 2; mt++) {
                    mma16816(acc[mt][0], af[0][mt][k], bf + 0);
                    mma16816(acc[mt][1], af[0][mt][k], bf + 2);
                }
            }
#pragma unroll
            for (int mt = 0; mt < 2; mt++)
#pragma unroll
                for (int nb = 0; nb < 2; nb++) {
                    int ncol = tile * 64 + npair * 16 + nb * 8 + 2 * (lane & 3);
                    float s0 = scn[ncol], s1 = scn[ncol + 1];
                    float v;
                    v = acc[mt][nb][0] - s0;
                    if (v > best[2*mt])   { best[2*mt] = v;   idx[2*mt] = ncol; }
                    v = acc[mt][nb][1] - s1;
                    if (v > best[2*mt])   { best[2*mt] = v;   idx[2*mt] = ncol + 1; }
                    v = acc[mt][nb][2] - s0;
                    if (v > best[2*mt+1]) { best[2*mt+1] = v; idx[2*mt+1] = ncol; }
                    v = acc[mt][nb][3] - s1;
                    if (v > best[2*mt+1]) { best[2*mt+1] = v; idx[2*mt+1] = ncol + 1; }
                }
        }
        __syncthreads();
    }

    // quad reduce (tie -> lower index)
#pragma unroll
    for (int slot = 0; slot < 4; slot++) {
#pragma unroll
        for (int off = 1; off <= 2; off <<= 1) {
            float ob = __shfl_xor_sync(0xffffffffu, best[slot], off);
            int oi = __shfl_xor_sync(0xffffffffu, idx[slot], off);
            if (ob > best[slot] || (ob == best[slot] && oi < idx[slot])) {
                best[slot] = ob; idx[slot] = oi;
            }
        }
    }

    const float* svn = reinterpret_cast<const float*>(smem + SM_VN);
    float errsum = 0.f;
#pragma unroll
    for (int slot = 0; slot < 4; slot++) {
        int row = wid * 32 + (slot >> 1) * 16 + (slot & 1) * 8 + (lane >> 2);
        int n = cta * M_TILE + row;
        const float4* c = reinterpret_cast<const float4*>(g_c + (size_t)idx[slot] * NK);
        float4* o = reinterpret_cast<float4*>(out + (size_t)n * NK);
#pragma unroll
        for (int j = lane & 3; j < 16; j += 4) o[j] = c[j];
        if ((lane & 3) == 0) {
            float err = fmaxf(svn[row] - 2.0f * best[slot], 0.0f);
            out[OFF_Z + n] = (float)idx[slot];
            out[OFF_ERR + n] = err;
            errsum += err;
        }
    }
#pragma unroll
    for (int o = 16; o; o >>= 1) errsum += __shfl_xor_sync(0xffffffffu, errsum, o);
    float* red = reinterpret_cast<float*>(smem + SM_RED);
    if (lane == 0) red[wid] = errsum;
    __syncthreads();
    if (tid == 0)
        g_partial[cta] = ((red[0] + red[1]) + (red[2] + red[3]))
                       + ((red[4] + red[5]) + (red[6] + red[7]));

    // fused finalize: last CTA reduces all partials (fixed deterministic order)
    __shared__ int s_last;
    if (tid == 0) {
        __threadfence();
        s_last = (atomicAdd(&g_done, 1) == NCTA - 1);
    }
    __syncthreads();
    if (s_last) {
        __threadfence();
        float* fred = reinterpret_cast<float*>(smem + SM_A);
        fred[tid] = g_partial[tid];
        __syncthreads();
#pragma unroll
        for (int off = 128; off > 0; off >>= 1) {
            if (tid < off) fred[tid] += fred[tid + off];
            __syncthreads();
        }
        if (tid == 0) {
            out[OFF_COMMIT] = fred[0] * (1.0f / (float)NVEC);
            out[OFF_CB] = 0.0f;   // l_codebook is identically 0 in forward value
        }
    }
}

extern "C" void kernel_launch(void* const* d_in, const int* in_sizes, int n_in,
                              void* d_out, int out_size) {
    const float* vecs    = (const float*)d_in[0];
    const float* c_sum   = (const float*)d_in[1];
    const float* c_count = (const float*)d_in[2];
    float* out = (float*)d_out;

    cudaFuncSetAttribute(vq_mma, cudaFuncAttributeMaxDynamicSharedMemorySize, SM_TOT);

    vq_prep_code<<<128, 128>>>(c_sum, c_count);
    vq_mma<<<NCTA, NTHR, SM_TOT>>>(vecs, out);
}